// round 4
// baseline (speedup 1.0000x reference)
#include <cuda_runtime.h>
#include <cuda_bf16.h>
#include <math.h>
#include <stdint.h>

#define T_SEQ 2048
#define D_MODEL 1024
#define N_HEADS 16
#define HEAD_DIM 64
#define FFN_DIM 4096

// ---------------- scratch ----------------
__device__ float g_xn[T_SEQ * D_MODEL];
__device__ float g_q[T_SEQ * D_MODEL];
__device__ float g_k[T_SEQ * D_MODEL];
__device__ float g_v[T_SEQ * D_MODEL];
__device__ float g_attn[T_SEQ * D_MODEL];
__device__ float g_x1[T_SEQ * D_MODEL];
__device__ float g_h[T_SEQ * FFN_DIM];

// ---------------- helpers ----------------
__device__ __forceinline__ uint32_t smem_u32(const void* p) {
    uint32_t a;
    asm("{ .reg .u64 t; cvta.to.shared.u64 t, %1; cvt.u32.u64 %0, t; }" : "=r"(a) : "l"(p));
    return a;
}
__device__ __forceinline__ void cp16(uint32_t s, const void* g) {
    asm volatile("cp.async.cg.shared.global [%0], [%1], 16;" :: "r"(s), "l"(g));
}
#define CP_COMMIT() asm volatile("cp.async.commit_group;" ::: "memory")
#define CP_WAIT(n)  asm volatile("cp.async.wait_group %0;" :: "n"(n) : "memory")

__device__ __forceinline__ void mma_tf32(float* d, const uint32_t* a, const uint32_t* b) {
    asm volatile(
        "mma.sync.aligned.m16n8k8.row.col.f32.tf32.tf32.f32 "
        "{%0,%1,%2,%3}, {%4,%5,%6,%7}, {%8,%9}, {%0,%1,%2,%3};"
        : "+f"(d[0]), "+f"(d[1]), "+f"(d[2]), "+f"(d[3])
        : "r"(a[0]), "r"(a[1]), "r"(a[2]), "r"(a[3]), "r"(b[0]), "r"(b[1]));
}
// split fp32 into tf32 hi + fp32 lo remainder (tf32x3 trick)
__device__ __forceinline__ void split_tf32(float v, uint32_t& hi, uint32_t& lo) {
    uint32_t h;
    asm("cvt.rna.tf32.f32 %0, %1;" : "=r"(h) : "f"(v));
    hi = h;
    lo = __float_as_uint(v - __uint_as_float(h));
}
// fast e^x via FMA poly (avoids MUFU bottleneck). Valid for x <= 0 side; clamps underflow.
__device__ __forceinline__ float fexp(float x) {
    float y = fmaxf(x * 1.4426950408889634f, -125.0f);
    float r = rintf(y);
    float f = y - r;
    float p = 1.3333558146e-3f;
    p = fmaf(p, f, 9.6181291076e-3f);
    p = fmaf(p, f, 5.5504108665e-2f);
    p = fmaf(p, f, 2.4022650696e-1f);
    p = fmaf(p, f, 6.9314718056e-1f);
    p = fmaf(p, f, 1.0f);
    return __int_as_float(__float_as_int(p) + (((int)r) << 23));
}

// ---------------- LayerNorm ----------------
__global__ void ln_kernel(const float* __restrict__ x, const float* __restrict__ g,
                          const float* __restrict__ b, float* __restrict__ y) {
    int row = blockIdx.x;
    const float* xr = x + row * D_MODEL;
    float s = 0.f, s2 = 0.f;
    for (int c = threadIdx.x; c < D_MODEL; c += 256) {
        float v = xr[c];
        s += v; s2 += v * v;
    }
    __shared__ float red0[32], red1[32];
    #pragma unroll
    for (int o = 16; o > 0; o >>= 1) {
        s  += __shfl_down_sync(0xffffffffu, s, o);
        s2 += __shfl_down_sync(0xffffffffu, s2, o);
    }
    int w = threadIdx.x >> 5, l = threadIdx.x & 31;
    if (l == 0) { red0[w] = s; red1[w] = s2; }
    __syncthreads();
    if (w == 0) {
        s  = (l < 8) ? red0[l] : 0.f;
        s2 = (l < 8) ? red1[l] : 0.f;
        #pragma unroll
        for (int o = 4; o > 0; o >>= 1) {
            s  += __shfl_down_sync(0xffffffffu, s, o);
            s2 += __shfl_down_sync(0xffffffffu, s2, o);
        }
        if (l == 0) { red0[0] = s; red1[0] = s2; }
    }
    __syncthreads();
    float mu  = red0[0] * (1.f / D_MODEL);
    float var = red1[0] * (1.f / D_MODEL) - mu * mu;
    float inv = rsqrtf(var + 1e-5f);
    float* yr = y + row * D_MODEL;
    for (int c = threadIdx.x; c < D_MODEL; c += 256)
        yr[c] = (xr[c] - mu) * inv * g[c] + b[c];
}

// ---------------- tf32x3 mma GEMM ----------------
#define A_STRIDE 36
#define B_STRIDE 136
#define A_BYTES (128 * A_STRIDE * 4)
#define B_BYTES (32 * B_STRIDE * 4)
#define STAGE_BYTES (A_BYTES + B_BYTES)
#define SMEM_GEMM (2 * STAGE_BYTES)

template<int ACT, bool HAS_RES>
__global__ void __launch_bounds__(256, 2)
mma_gemm(const float* __restrict__ A,
         const float* __restrict__ W0, const float* __restrict__ W1, const float* __restrict__ W2,
         const float* __restrict__ b0, const float* __restrict__ b1, const float* __restrict__ b2,
         const float* __restrict__ Res,
         float* __restrict__ C0, float* __restrict__ C1, float* __restrict__ C2,
         int N, int K) {
    extern __shared__ char smem[];
    const int z = blockIdx.z;
    const float* W    = (z == 0) ? W0 : (z == 1) ? W1 : W2;
    const float* bias = (z == 0) ? b0 : (z == 1) ? b1 : b2;
    float* C          = (z == 0) ? C0 : (z == 1) ? C1 : C2;

    const int m0 = blockIdx.y * 128;
    const int n0 = blockIdx.x * 128;
    const int tid = threadIdx.x;
    const int wid = tid >> 5, lane = tid & 31;
    const int wrow = wid & 3;
    const int wcol = wid >> 2;
    const int lr = lane >> 2;
    const int lc = lane & 3;

    const uint32_t sbase = smem_u32(smem);
    const int NKB = K >> 5;

    auto load_stage = [&](int kb, int s) {
        const int k0 = kb << 5;
        const uint32_t sA = sbase + s * STAGE_BYTES;
        const uint32_t sB = sA + A_BYTES;
        #pragma unroll
        for (int j = 0; j < 4; ++j) {
            const int f = tid * 4 + j;
            const int r = f >> 3, c = (f & 7) << 2;
            cp16(sA + (uint32_t)r * 144u + (uint32_t)c * 4u,
                 A + (size_t)(m0 + r) * K + k0 + c);
        }
        #pragma unroll
        for (int j = 0; j < 4; ++j) {
            const int f = tid * 4 + j;
            const int r = f >> 5, c = (f & 31) << 2;
            cp16(sB + (uint32_t)r * 544u + (uint32_t)c * 4u,
                 W + (size_t)(k0 + r) * N + n0 + c);
        }
    };

    float acc[2][8][4];
    #pragma unroll
    for (int mt = 0; mt < 2; ++mt)
        #pragma unroll
        for (int nt = 0; nt < 8; ++nt)
            #pragma unroll
            for (int i = 0; i < 4; ++i) acc[mt][nt][i] = 0.f;

    load_stage(0, 0);
    CP_COMMIT();

    for (int kb = 0; kb < NKB; ++kb) {
        const int s = kb & 1;
        if (kb + 1 < NKB) {
            load_stage(kb + 1, s ^ 1);
            CP_COMMIT();
            CP_WAIT(1);
        } else {
            CP_WAIT(0);
        }
        __syncthreads();

        const float* Asf = (const float*)(smem + s * STAGE_BYTES);
        const float* Bsf = (const float*)(smem + s * STAGE_BYTES + A_BYTES);

        #pragma unroll
        for (int ks = 0; ks < 4; ++ks) {
            uint32_t ah[2][4], al[2][4];
            const int c = ks * 8 + lc;
            #pragma unroll
            for (int mt = 0; mt < 2; ++mt) {
                const int r = wrow * 32 + mt * 16 + lr;
                split_tf32(Asf[r * A_STRIDE + c],           ah[mt][0], al[mt][0]);
                split_tf32(Asf[(r + 8) * A_STRIDE + c],     ah[mt][1], al[mt][1]);
                split_tf32(Asf[r * A_STRIDE + c + 4],       ah[mt][2], al[mt][2]);
                split_tf32(Asf[(r + 8) * A_STRIDE + c + 4], ah[mt][3], al[mt][3]);
            }
            #pragma unroll
            for (int nt = 0; nt < 8; ++nt) {
                const int n = wcol * 64 + nt * 8 + lr;
                uint32_t bh[2], bl[2];
                split_tf32(Bsf[c * B_STRIDE + n],       bh[0], bl[0]);
                split_tf32(Bsf[(c + 4) * B_STRIDE + n], bh[1], bl[1]);
                #pragma unroll
                for (int mt = 0; mt < 2; ++mt) {
                    mma_tf32(acc[mt][nt], ah[mt], bh);
                    mma_tf32(acc[mt][nt], al[mt], bh);
                    mma_tf32(acc[mt][nt], ah[mt], bl);
                }
            }
        }
        __syncthreads();
    }

    #pragma unroll
    for (int nt = 0; nt < 8; ++nt) {
        const int col = n0 + wcol * 64 + nt * 8 + lc * 2;
        const float2 bv = *(const float2*)&bias[col];
        #pragma unroll
        for (int mt = 0; mt < 2; ++mt) {
            const int row = m0 + wrow * 32 + mt * 16 + lr;
            #pragma unroll
            for (int half = 0; half < 2; ++half) {
                const int r = row + half * 8;
                float vx = acc[mt][nt][half * 2 + 0] + bv.x;
                float vy = acc[mt][nt][half * 2 + 1] + bv.y;
                if (ACT == 1) {
                    vx = 0.5f * vx * (1.0f + erff(vx * 0.7071067811865475f));
                    vy = 0.5f * vy * (1.0f + erff(vy * 0.7071067811865475f));
                }
                if (HAS_RES) {
                    float2 rv = *(const float2*)&Res[(size_t)r * N + col];
                    vx += rv.x; vy += rv.y;
                }
                float2 o; o.x = vx; o.y = vy;
                *(float2*)&C[(size_t)r * N + col] = o;
            }
        }
    }
}

// ---------------- flash attention on mma.sync tf32 ----------------
// CTA: 128 q-rows x 1 head. 256 threads, 8 warps (4 row x 2 col).
// SMEM floats: Qs[128][68], Ks[128][68], VsT[64][132], Ss[128][132], stats 3x128.
#define AT_QS   0
#define AT_KS   (128 * 68)
#define AT_VST  (AT_KS + 128 * 68)
#define AT_SS   (AT_VST + 64 * 132)
#define AT_MST  (AT_SS + 128 * 132)
#define AT_FLOATS (AT_MST + 3 * 128)
#define SMEM_ATTN (AT_FLOATS * 4)

__global__ void __launch_bounds__(256, 1)
attn_mma(const float* __restrict__ Q, const float* __restrict__ K,
         const float* __restrict__ V, float* __restrict__ O) {
    extern __shared__ float sm[];
    float* Qs   = sm + AT_QS;    // [128][68]
    float* Ks   = sm + AT_KS;    // [128][68]
    float* VsT  = sm + AT_VST;   // [64][132]  (V transposed: [d][kpos])
    float* Ss   = sm + AT_SS;    // [128][132]
    float* m_sh = sm + AT_MST;
    float* l_sh = m_sh + 128;
    float* a_sh = l_sh + 128;

    const int qb = gridDim.x - 1 - blockIdx.x;   // heavy tiles first
    const int h  = blockIdx.y;
    const int tid = threadIdx.x;
    const int wid = tid >> 5, lane = tid & 31;
    const int lr = lane >> 2, lc = lane & 3;
    const int wrow = wid & 3, wcol = wid >> 2;

    // load Q tile, pre-scaled by 1/sqrt(hd)=0.125
    #pragma unroll
    for (int i = 0; i < 8; ++i) {
        int f = tid + i * 256;
        int r = f >> 4, c4 = (f & 15) << 2;
        float4 v = *(const float4*)&Q[(size_t)(qb * 128 + r) * D_MODEL + h * 64 + c4];
        float* dst = &Qs[r * 68 + c4];
        dst[0] = v.x * 0.125f; dst[1] = v.y * 0.125f;
        dst[2] = v.z * 0.125f; dst[3] = v.w * 0.125f;
    }
    if (tid < 128) { m_sh[tid] = -1e30f; l_sh[tid] = 0.f; }

    float o_acc[2][4][4] = {};
    const float slope = exp2f(-0.5f * (float)(h + 1));

    for (int kb = 0; kb <= qb; ++kb) {
        __syncthreads();   // prior iter's mma reads of Ks/VsT/Ss complete
        // K tile
        #pragma unroll
        for (int i = 0; i < 8; ++i) {
            int f = tid + i * 256;
            int r = f >> 4, c4 = (f & 15) << 2;
            float4 v = *(const float4*)&K[(size_t)(kb * 128 + r) * D_MODEL + h * 64 + c4];
            float* dst = &Ks[r * 68 + c4];
            dst[0] = v.x; dst[1] = v.y; dst[2] = v.z; dst[3] = v.w;
        }
        // V tile transposed: VsT[d][k]
        {
            const int d = tid & 63, k0 = tid >> 6;
            const float* vp = V + (size_t)(kb * 128 + k0) * D_MODEL + h * 64 + d;
            #pragma unroll
            for (int i = 0; i < 32; ++i)
                VsT[d * 132 + k0 + i * 4] = vp[(size_t)i * 4 * D_MODEL];
        }
        __syncthreads();

        // ---- S = Q @ K^T (tf32 mma) ----
        float s_acc[2][8][4] = {};
        #pragma unroll
        for (int ks = 0; ks < 8; ++ks) {
            uint32_t a[2][4];
            const int c = ks * 8 + lc;
            #pragma unroll
            for (int mt = 0; mt < 2; ++mt) {
                const int r = wrow * 32 + mt * 16 + lr;
                a[mt][0] = __float_as_uint(Qs[r * 68 + c]);
                a[mt][1] = __float_as_uint(Qs[(r + 8) * 68 + c]);
                a[mt][2] = __float_as_uint(Qs[r * 68 + c + 4]);
                a[mt][3] = __float_as_uint(Qs[(r + 8) * 68 + c + 4]);
            }
            #pragma unroll
            for (int nt = 0; nt < 8; ++nt) {
                const int n = wcol * 64 + nt * 8 + lr;
                uint32_t b[2];
                b[0] = __float_as_uint(Ks[n * 68 + c]);
                b[1] = __float_as_uint(Ks[n * 68 + c + 4]);
                mma_tf32(s_acc[0][nt], a[0], b);
                mma_tf32(s_acc[1][nt], a[1], b);
            }
        }
        // store S frags to Ss
        #pragma unroll
        for (int mt = 0; mt < 2; ++mt) {
            const int r = wrow * 32 + mt * 16 + lr;
            #pragma unroll
            for (int nt = 0; nt < 8; ++nt) {
                const int col = wcol * 64 + nt * 8 + 2 * lc;
                float2 v0; v0.x = s_acc[mt][nt][0]; v0.y = s_acc[mt][nt][1];
                float2 v1; v1.x = s_acc[mt][nt][2]; v1.y = s_acc[mt][nt][3];
                *(float2*)&Ss[r * 132 + col] = v0;
                *(float2*)&Ss[(r + 8) * 132 + col] = v1;
            }
        }
        __syncthreads();

        // ---- online softmax: 2 threads per row, FMA exp ----
        {
            const int row = tid >> 1, half = tid & 1;
            const int qq = qb * 128 + row;
            const int colbase = half * 64;
            float mx = -1e30f;
            #pragma unroll
            for (int c4 = 0; c4 < 64; c4 += 4) {
                float4 s4 = *(float4*)&Ss[row * 132 + colbase + c4];
                const int kk = kb * 128 + colbase + c4;
                s4.x = (kk     <= qq) ? fmaf(slope, (float)(kk     - qq), s4.x) : -1e30f;
                s4.y = (kk + 1 <= qq) ? fmaf(slope, (float)(kk + 1 - qq), s4.y) : -1e30f;
                s4.z = (kk + 2 <= qq) ? fmaf(slope, (float)(kk + 2 - qq), s4.z) : -1e30f;
                s4.w = (kk + 3 <= qq) ? fmaf(slope, (float)(kk + 3 - qq), s4.w) : -1e30f;
                *(float4*)&Ss[row * 132 + colbase + c4] = s4;
                mx = fmaxf(mx, fmaxf(fmaxf(s4.x, s4.y), fmaxf(s4.z, s4.w)));
            }
            mx = fmaxf(mx, __shfl_xor_sync(0xffffffffu, mx, 1));
            const float m_old = m_sh[row];
            const float m_new = fmaxf(m_old, mx);
            float sum = 0.f;
            #pragma unroll
            for (int c4 = 0; c4 < 64; c4 += 4) {
                float4 s4 = *(float4*)&Ss[row * 132 + colbase + c4];
                s4.x = fexp(s4.x - m_new); s4.y = fexp(s4.y - m_new);
                s4.z = fexp(s4.z - m_new); s4.w = fexp(s4.w - m_new);
                *(float4*)&Ss[row * 132 + colbase + c4] = s4;
                sum += (s4.x + s4.y) + (s4.z + s4.w);
            }
            sum += __shfl_xor_sync(0xffffffffu, sum, 1);
            if (half == 0) {
                const float alpha = fexp(m_old - m_new);
                m_sh[row] = m_new;
                l_sh[row] = l_sh[row] * alpha + sum;
                a_sh[row] = alpha;
            }
        }
        __syncthreads();

        // ---- rescale O, then O += P @ V ----
        #pragma unroll
        for (int mt = 0; mt < 2; ++mt) {
            const float a0 = a_sh[wrow * 32 + mt * 16 + lr];
            const float a1 = a_sh[wrow * 32 + mt * 16 + lr + 8];
            #pragma unroll
            for (int nt = 0; nt < 4; ++nt) {
                o_acc[mt][nt][0] *= a0; o_acc[mt][nt][1] *= a0;
                o_acc[mt][nt][2] *= a1; o_acc[mt][nt][3] *= a1;
            }
        }
        #pragma unroll
        for (int ks = 0; ks < 16; ++ks) {
            uint32_t a[2][4];
            const int c = ks * 8 + lc;
            #pragma unroll
            for (int mt = 0; mt < 2; ++mt) {
                const int r = wrow * 32 + mt * 16 + lr;
                a[mt][0] = __float_as_uint(Ss[r * 132 + c]);
                a[mt][1] = __float_as_uint(Ss[(r + 8) * 132 + c]);
                a[mt][2] = __float_as_uint(Ss[r * 132 + c + 4]);
                a[mt][3] = __float_as_uint(Ss[(r + 8) * 132 + c + 4]);
            }
            #pragma unroll
            for (int nt = 0; nt < 4; ++nt) {
                const int n = wcol * 32 + nt * 8 + lr;
                uint32_t b[2];
                b[0] = __float_as_uint(VsT[n * 132 + c]);
                b[1] = __float_as_uint(VsT[n * 132 + c + 4]);
                mma_tf32(o_acc[0][nt], a[0], b);
                mma_tf32(o_acc[1][nt], a[1], b);
            }
        }
    }

    // epilogue: O / l
    #pragma unroll
    for (int mt = 0; mt < 2; ++mt) {
        const int r = wrow * 32 + mt * 16 + lr;
        const float inv0 = 1.f / l_sh[r];
        const float inv1 = 1.f / l_sh[r + 8];
        #pragma unroll
        for (int nt = 0; nt < 4; ++nt) {
            const int col = h * 64 + wcol * 32 + nt * 8 + 2 * lc;
            float2 v0; v0.x = o_acc[mt][nt][0] * inv0; v0.y = o_acc[mt][nt][1] * inv0;
            float2 v1; v1.x = o_acc[mt][nt][2] * inv1; v1.y = o_acc[mt][nt][3] * inv1;
            *(float2*)&O[(size_t)(qb * 128 + r) * D_MODEL + col] = v0;
            *(float2*)&O[(size_t)(qb * 128 + r + 8) * D_MODEL + col] = v1;
        }
    }
}

// ---------------- launch ----------------
extern "C" void kernel_launch(void* const* d_in, const int* in_sizes, int n_in,
                              void* d_out, int out_size) {
    const float* x   = (const float*)d_in[0];
    const float* wq  = (const float*)d_in[3];
    const float* bq  = (const float*)d_in[4];
    const float* wk  = (const float*)d_in[5];
    const float* bk  = (const float*)d_in[6];
    const float* wv  = (const float*)d_in[7];
    const float* bv  = (const float*)d_in[8];
    const float* wo  = (const float*)d_in[9];
    const float* bo  = (const float*)d_in[10];
    const float* w1  = (const float*)d_in[11];
    const float* b1  = (const float*)d_in[12];
    const float* w2  = (const float*)d_in[13];
    const float* b2  = (const float*)d_in[14];
    const float* g1  = (const float*)d_in[15];
    const float* be1 = (const float*)d_in[16];
    const float* g2  = (const float*)d_in[17];
    const float* be2 = (const float*)d_in[18];
    float* out = (float*)d_out;

    float *p_xn, *p_q, *p_k, *p_v, *p_attn, *p_x1, *p_h;
    cudaGetSymbolAddress((void**)&p_xn,   g_xn);
    cudaGetSymbolAddress((void**)&p_q,    g_q);
    cudaGetSymbolAddress((void**)&p_k,    g_k);
    cudaGetSymbolAddress((void**)&p_v,    g_v);
    cudaGetSymbolAddress((void**)&p_attn, g_attn);
    cudaGetSymbolAddress((void**)&p_x1,   g_x1);
    cudaGetSymbolAddress((void**)&p_h,    g_h);

    cudaFuncSetAttribute(mma_gemm<0, false>, cudaFuncAttributeMaxDynamicSharedMemorySize, SMEM_GEMM);
    cudaFuncSetAttribute(mma_gemm<0, true>,  cudaFuncAttributeMaxDynamicSharedMemorySize, SMEM_GEMM);
    cudaFuncSetAttribute(mma_gemm<1, false>, cudaFuncAttributeMaxDynamicSharedMemorySize, SMEM_GEMM);
    cudaFuncSetAttribute(attn_mma, cudaFuncAttributeMaxDynamicSharedMemorySize, SMEM_ATTN);

    // LN1
    ln_kernel<<<T_SEQ, 256>>>(x, g1, be1, p_xn);

    // fused QKV
    mma_gemm<0, false><<<dim3(D_MODEL / 128, T_SEQ / 128, 3), 256, SMEM_GEMM>>>(
        p_xn, wq, wk, wv, bq, bk, bv, nullptr, p_q, p_k, p_v, D_MODEL, D_MODEL);

    // attention (tensor-core flash)
    attn_mma<<<dim3(T_SEQ / 128, N_HEADS), 256, SMEM_ATTN>>>(p_q, p_k, p_v, p_attn);

    // O projection + residual
    mma_gemm<0, true><<<dim3(D_MODEL / 128, T_SEQ / 128, 1), 256, SMEM_GEMM>>>(
        p_attn, wo, wo, wo, bo, bo, bo, x, p_x1, p_x1, p_x1, D_MODEL, D_MODEL);

    // LN2
    ln_kernel<<<T_SEQ, 256>>>(p_x1, g2, be2, p_xn);

    // FFN1 + GELU
    mma_gemm<1, false><<<dim3(FFN_DIM / 128, T_SEQ / 128, 1), 256, SMEM_GEMM>>>(
        p_xn, w1, w1, w1, b1, b1, b1, nullptr, p_h, p_h, p_h, FFN_DIM, D_MODEL);

    // FFN2 + residual -> out
    mma_gemm<0, true><<<dim3(D_MODEL / 128, T_SEQ / 128, 1), 256, SMEM_GEMM>>>(
        p_h, w2, w2, w2, b2, b2, b2, p_x1, out, out, out, D_MODEL, FFN_DIM);
}

// round 5
// speedup vs baseline: 1.5545x; 1.5545x over previous
#include <cuda_runtime.h>
#include <cuda_bf16.h>
#include <math.h>
#include <stdint.h>

#define T_SEQ 2048
#define D_MODEL 1024
#define N_HEADS 16
#define HEAD_DIM 64
#define FFN_DIM 4096
typedef __nv_bfloat16 bf16;

// ---------------- scratch ----------------
__device__ float g_q[T_SEQ * D_MODEL];
__device__ float g_k[T_SEQ * D_MODEL];
__device__ float g_v[T_SEQ * D_MODEL];
__device__ float g_x1[T_SEQ * D_MODEL];
__device__ bf16  g_xnh[T_SEQ * D_MODEL];
__device__ bf16  g_xnl[T_SEQ * D_MODEL];
__device__ bf16  g_ah[T_SEQ * D_MODEL];
__device__ bf16  g_al[T_SEQ * D_MODEL];
__device__ bf16  g_hh[T_SEQ * FFN_DIM];
__device__ bf16  g_hl[T_SEQ * FFN_DIM];
// transposed pre-split weights [N][K]
__device__ bf16 g_wqh[D_MODEL * D_MODEL], g_wql[D_MODEL * D_MODEL];
__device__ bf16 g_wkh[D_MODEL * D_MODEL], g_wkl[D_MODEL * D_MODEL];
__device__ bf16 g_wvh[D_MODEL * D_MODEL], g_wvl[D_MODEL * D_MODEL];
__device__ bf16 g_woh[D_MODEL * D_MODEL], g_wol[D_MODEL * D_MODEL];
__device__ bf16 g_w1h[FFN_DIM * D_MODEL], g_w1l[FFN_DIM * D_MODEL];
__device__ bf16 g_w2h[D_MODEL * FFN_DIM], g_w2l[D_MODEL * FFN_DIM];

// ---------------- helpers ----------------
__device__ __forceinline__ uint32_t smem_u32(const void* p) {
    uint32_t a;
    asm("{ .reg .u64 t; cvta.to.shared.u64 t, %1; cvt.u32.u64 %0, t; }" : "=r"(a) : "l"(p));
    return a;
}
__device__ __forceinline__ void cp16(uint32_t s, const void* g) {
    asm volatile("cp.async.cg.shared.global [%0], [%1], 16;" :: "r"(s), "l"(g));
}
#define CP_COMMIT() asm volatile("cp.async.commit_group;" ::: "memory")
#define CP_WAIT(n)  asm volatile("cp.async.wait_group %0;" :: "n"(n) : "memory")

__device__ __forceinline__ void mma_bf16(float* d, const uint32_t* a, const uint32_t* b) {
    asm volatile(
        "mma.sync.aligned.m16n8k16.row.col.f32.bf16.bf16.f32 "
        "{%0,%1,%2,%3}, {%4,%5,%6,%7}, {%8,%9}, {%0,%1,%2,%3};"
        : "+f"(d[0]), "+f"(d[1]), "+f"(d[2]), "+f"(d[3])
        : "r"(a[0]), "r"(a[1]), "r"(a[2]), "r"(a[3]), "r"(b[0]), "r"(b[1]));
}
__device__ __forceinline__ void mma_tf32(float* d, const uint32_t* a, const uint32_t* b) {
    asm volatile(
        "mma.sync.aligned.m16n8k8.row.col.f32.tf32.tf32.f32 "
        "{%0,%1,%2,%3}, {%4,%5,%6,%7}, {%8,%9}, {%0,%1,%2,%3};"
        : "+f"(d[0]), "+f"(d[1]), "+f"(d[2]), "+f"(d[3])
        : "r"(a[0]), "r"(a[1]), "r"(a[2]), "r"(a[3]), "r"(b[0]), "r"(b[1]));
}
__device__ __forceinline__ uint32_t bfpack(float a, float b) {
    __nv_bfloat162 t = __floats2bfloat162_rn(a, b);
    return *reinterpret_cast<uint32_t*>(&t);
}
__device__ __forceinline__ float bfhi(float v) {
    return __bfloat162float(__float2bfloat16(v));
}
// fast e^x via FMA poly
__device__ __forceinline__ float fexp(float x) {
    float y = fmaxf(x * 1.4426950408889634f, -125.0f);
    float r = rintf(y);
    float f = y - r;
    float p = 1.3333558146e-3f;
    p = fmaf(p, f, 9.6181291076e-3f);
    p = fmaf(p, f, 5.5504108665e-2f);
    p = fmaf(p, f, 2.4022650696e-1f);
    p = fmaf(p, f, 6.9314718056e-1f);
    p = fmaf(p, f, 1.0f);
    return __int_as_float(__float_as_int(p) + (((int)r) << 23));
}

// ---------------- weight convert: W[K][N] fp32 -> Wt[N][K] bf16 hi/lo ----------------
__global__ void wconv(const float* __restrict__ W, bf16* __restrict__ Th,
                      bf16* __restrict__ Tl, int K, int N) {
    __shared__ float t[32][33];
    const int k0 = blockIdx.y * 32, n0 = blockIdx.x * 32;
    const int tx = threadIdx.x, ty = threadIdx.y;   // 32 x 8
    #pragma unroll
    for (int j = 0; j < 4; ++j)
        t[ty + 8 * j][tx] = W[(size_t)(k0 + ty + 8 * j) * N + n0 + tx];
    __syncthreads();
    #pragma unroll
    for (int j = 0; j < 4; ++j) {
        const float v = t[tx][ty + 8 * j];
        const float h = bfhi(v);
        Th[(size_t)(n0 + ty + 8 * j) * K + k0 + tx] = __float2bfloat16(v);
        Tl[(size_t)(n0 + ty + 8 * j) * K + k0 + tx] = __float2bfloat16(v - h);
    }
}

// ---------------- LayerNorm -> bf16 hi/lo ----------------
__global__ void ln_kernel(const float* __restrict__ x, const float* __restrict__ g,
                          const float* __restrict__ b, bf16* __restrict__ yh,
                          bf16* __restrict__ yl) {
    const int row = blockIdx.x, tid = threadIdx.x;
    const float4 xv = *(const float4*)&x[(size_t)row * D_MODEL + tid * 4];
    float s  = (xv.x + xv.y) + (xv.z + xv.w);
    float s2 = (xv.x * xv.x + xv.y * xv.y) + (xv.z * xv.z + xv.w * xv.w);
    __shared__ float red0[8], red1[8];
    #pragma unroll
    for (int o = 16; o > 0; o >>= 1) {
        s  += __shfl_down_sync(0xffffffffu, s, o);
        s2 += __shfl_down_sync(0xffffffffu, s2, o);
    }
    const int w = tid >> 5, l = tid & 31;
    if (l == 0) { red0[w] = s; red1[w] = s2; }
    __syncthreads();
    if (w == 0) {
        s  = (l < 8) ? red0[l] : 0.f;
        s2 = (l < 8) ? red1[l] : 0.f;
        #pragma unroll
        for (int o = 4; o > 0; o >>= 1) {
            s  += __shfl_down_sync(0xffffffffu, s, o);
            s2 += __shfl_down_sync(0xffffffffu, s2, o);
        }
        if (l == 0) { red0[0] = s; red1[0] = s2; }
    }
    __syncthreads();
    const float mu  = red0[0] * (1.f / D_MODEL);
    const float var = red1[0] * (1.f / D_MODEL) - mu * mu;
    const float inv = rsqrtf(var + 1e-5f);
    const float4 gv = *(const float4*)&g[tid * 4];
    const float4 bv = *(const float4*)&b[tid * 4];
    float o0 = (xv.x - mu) * inv * gv.x + bv.x;
    float o1 = (xv.y - mu) * inv * gv.y + bv.y;
    float o2 = (xv.z - mu) * inv * gv.z + bv.z;
    float o3 = (xv.w - mu) * inv * gv.w + bv.w;
    uint2 H, L;
    H.x = bfpack(o0, o1); H.y = bfpack(o2, o3);
    L.x = bfpack(o0 - bfhi(o0), o1 - bfhi(o1));
    L.y = bfpack(o2 - bfhi(o2), o3 - bfhi(o3));
    *(uint2*)&yh[(size_t)row * D_MODEL + tid * 4] = H;
    *(uint2*)&yl[(size_t)row * D_MODEL + tid * 4] = L;
}

// ---------------- bf16x3 mma GEMM ----------------
// C = act(A @ W^T_t + bias) (+Res). A: [M][K] bf16 hi/lo, Wt: [N][K] bf16 hi/lo.
// Tile 128x128x32, 8 warps (4x2), m16n8k16, double-buffered cp.async.
// SMEM per stage: 4 arrays x 128 rows x 80B (stride 40 bf16, conflict-free: 20*lr+lc).
#define GS 20
#define ARR_B (128 * 80)
#define STAGE_B (4 * ARR_B)
#define SMEM_G (2 * STAGE_B)

template<int ACT, bool HAS_RES, bool OUT_HILO>
__global__ void __launch_bounds__(256, 2)
bgemm(const bf16* __restrict__ Ah, const bf16* __restrict__ Al,
      const bf16* __restrict__ W0h, const bf16* __restrict__ W0l,
      const bf16* __restrict__ W1h, const bf16* __restrict__ W1l,
      const bf16* __restrict__ W2h, const bf16* __restrict__ W2l,
      const float* __restrict__ b0, const float* __restrict__ b1, const float* __restrict__ b2,
      const float* __restrict__ Res,
      void* __restrict__ C0, void* __restrict__ C1, void* __restrict__ C2,
      void* __restrict__ Clo,
      int N, int K) {
    extern __shared__ char smem[];
    const int z = blockIdx.z;
    const bf16* Wh   = (z == 0) ? W0h : (z == 1) ? W1h : W2h;
    const bf16* Wl   = (z == 0) ? W0l : (z == 1) ? W1l : W2l;
    const float* bias = (z == 0) ? b0 : (z == 1) ? b1 : b2;
    void* Cv          = (z == 0) ? C0 : (z == 1) ? C1 : C2;

    const int m0 = blockIdx.y * 128;
    const int n0 = blockIdx.x * 128;
    const int tid = threadIdx.x;
    const int wid = tid >> 5, lane = tid & 31;
    const int wrow = wid & 3, wcol = wid >> 2;
    const int lr = lane >> 2, lc = lane & 3;

    const uint32_t sbase = smem_u32(smem);
    const int NKB = K >> 5;

    auto load_stage = [&](int kb, int s) {
        const int k0 = kb << 5;
        const uint32_t st = sbase + s * STAGE_B;
        #pragma unroll
        for (int j = 0; j < 2; ++j) {
            const int f = tid * 2 + j;
            const int r = f >> 2, cc = f & 3;
            const uint32_t doff = (uint32_t)r * 80u + (uint32_t)cc * 16u;
            const size_t aoff = (size_t)(m0 + r) * K + k0 + cc * 8;
            const size_t boff = (size_t)(n0 + r) * K + k0 + cc * 8;
            cp16(st + doff,             Ah + aoff);
            cp16(st + ARR_B + doff,     Al + aoff);
            cp16(st + 2 * ARR_B + doff, Wh + boff);
            cp16(st + 3 * ARR_B + doff, Wl + boff);
        }
    };

    float acc[2][8][4];
    #pragma unroll
    for (int mt = 0; mt < 2; ++mt)
        #pragma unroll
        for (int nt = 0; nt < 8; ++nt)
            #pragma unroll
            for (int i = 0; i < 4; ++i) acc[mt][nt][i] = 0.f;

    load_stage(0, 0);
    CP_COMMIT();

    for (int kb = 0; kb < NKB; ++kb) {
        const int s = kb & 1;
        if (kb + 1 < NKB) {
            load_stage(kb + 1, s ^ 1);
            CP_COMMIT();
            CP_WAIT(1);
        } else {
            CP_WAIT(0);
        }
        __syncthreads();

        const uint32_t* AhW = (const uint32_t*)(smem + s * STAGE_B);
        const uint32_t* AlW = AhW + ARR_B / 4;
        const uint32_t* BhW = AhW + 2 * ARR_B / 4;
        const uint32_t* BlW = AhW + 3 * ARR_B / 4;

        #pragma unroll
        for (int kstep = 0; kstep < 2; ++kstep) {
            const int kw = kstep * 8 + lc;
            uint32_t ah[2][4], al[2][4];
            #pragma unroll
            for (int mt = 0; mt < 2; ++mt) {
                const int r = wrow * 32 + mt * 16 + lr;
                ah[mt][0] = AhW[r * GS + kw];
                ah[mt][1] = AhW[(r + 8) * GS + kw];
                ah[mt][2] = AhW[r * GS + kw + 4];
                ah[mt][3] = AhW[(r + 8) * GS + kw + 4];
                al[mt][0] = AlW[r * GS + kw];
                al[mt][1] = AlW[(r + 8) * GS + kw];
                al[mt][2] = AlW[r * GS + kw + 4];
                al[mt][3] = AlW[(r + 8) * GS + kw + 4];
            }
            #pragma unroll
            for (int nt = 0; nt < 8; ++nt) {
                const int n = wcol * 64 + nt * 8 + lr;
                uint32_t bh[2], bl[2];
                bh[0] = BhW[n * GS + kw];
                bh[1] = BhW[n * GS + kw + 4];
                bl[0] = BlW[n * GS + kw];
                bl[1] = BlW[n * GS + kw + 4];
                mma_bf16(acc[0][nt], ah[0], bh);
                mma_bf16(acc[1][nt], ah[1], bh);
                mma_bf16(acc[0][nt], al[0], bh);
                mma_bf16(acc[1][nt], al[1], bh);
                mma_bf16(acc[0][nt], ah[0], bl);
                mma_bf16(acc[1][nt], ah[1], bl);
            }
        }
        __syncthreads();
    }

    // epilogue
    #pragma unroll
    for (int nt = 0; nt < 8; ++nt) {
        const int col = n0 + wcol * 64 + nt * 8 + lc * 2;
        const float2 bv = *(const float2*)&bias[col];
        #pragma unroll
        for (int mt = 0; mt < 2; ++mt) {
            const int row = m0 + wrow * 32 + mt * 16 + lr;
            #pragma unroll
            for (int half = 0; half < 2; ++half) {
                const int r = row + half * 8;
                float vx = acc[mt][nt][half * 2 + 0] + bv.x;
                float vy = acc[mt][nt][half * 2 + 1] + bv.y;
                if (ACT == 1) {
                    vx = 0.5f * vx * (1.0f + erff(vx * 0.7071067811865475f));
                    vy = 0.5f * vy * (1.0f + erff(vy * 0.7071067811865475f));
                }
                if (HAS_RES) {
                    float2 rv = *(const float2*)&Res[(size_t)r * N + col];
                    vx += rv.x; vy += rv.y;
                }
                if (OUT_HILO) {
                    bf16* Ch = (bf16*)Cv;
                    bf16* Cl = (bf16*)Clo;
                    *(uint32_t*)&Ch[(size_t)r * N + col] = bfpack(vx, vy);
                    *(uint32_t*)&Cl[(size_t)r * N + col] =
                        bfpack(vx - bfhi(vx), vy - bfhi(vy));
                } else {
                    float2 o; o.x = vx; o.y = vy;
                    *(float2*)&((float*)Cv)[(size_t)r * N + col] = o;
                }
            }
        }
    }
}

// ---------------- flash attention on mma.sync tf32 (out: bf16 hi/lo) ----------------
#define AT_QS   0
#define AT_KS   (128 * 68)
#define AT_VST  (AT_KS + 128 * 68)
#define AT_SS   (AT_VST + 64 * 132)
#define AT_MST  (AT_SS + 128 * 132)
#define AT_FLOATS (AT_MST + 3 * 128)
#define SMEM_ATTN (AT_FLOATS * 4)

__global__ void __launch_bounds__(256, 1)
attn_mma(const float* __restrict__ Q, const float* __restrict__ K,
         const float* __restrict__ V, bf16* __restrict__ OH, bf16* __restrict__ OL) {
    extern __shared__ float sm[];
    float* Qs   = sm + AT_QS;
    float* Ks   = sm + AT_KS;
    float* VsT  = sm + AT_VST;
    float* Ss   = sm + AT_SS;
    float* m_sh = sm + AT_MST;
    float* l_sh = m_sh + 128;
    float* a_sh = l_sh + 128;

    const int qb = gridDim.x - 1 - blockIdx.x;
    const int h  = blockIdx.y;
    const int tid = threadIdx.x;
    const int wid = tid >> 5, lane = tid & 31;
    const int lr = lane >> 2, lc = lane & 3;
    const int wrow = wid & 3, wcol = wid >> 2;

    #pragma unroll
    for (int i = 0; i < 8; ++i) {
        int f = tid + i * 256;
        int r = f >> 4, c4 = (f & 15) << 2;
        float4 v = *(const float4*)&Q[(size_t)(qb * 128 + r) * D_MODEL + h * 64 + c4];
        float* dst = &Qs[r * 68 + c4];
        dst[0] = v.x * 0.125f; dst[1] = v.y * 0.125f;
        dst[2] = v.z * 0.125f; dst[3] = v.w * 0.125f;
    }
    if (tid < 128) { m_sh[tid] = -1e30f; l_sh[tid] = 0.f; }

    float o_acc[2][4][4] = {};
    const float slope = exp2f(-0.5f * (float)(h + 1));

    for (int kb = 0; kb <= qb; ++kb) {
        __syncthreads();
        #pragma unroll
        for (int i = 0; i < 8; ++i) {
            int f = tid + i * 256;
            int r = f >> 4, c4 = (f & 15) << 2;
            float4 v = *(const float4*)&K[(size_t)(kb * 128 + r) * D_MODEL + h * 64 + c4];
            float* dst = &Ks[r * 68 + c4];
            dst[0] = v.x; dst[1] = v.y; dst[2] = v.z; dst[3] = v.w;
        }
        {
            const int d = tid & 63, k0 = tid >> 6;
            const float* vp = V + (size_t)(kb * 128 + k0) * D_MODEL + h * 64 + d;
            #pragma unroll
            for (int i = 0; i < 32; ++i)
                VsT[d * 132 + k0 + i * 4] = vp[(size_t)i * 4 * D_MODEL];
        }
        __syncthreads();

        float s_acc[2][8][4] = {};
        #pragma unroll
        for (int ks = 0; ks < 8; ++ks) {
            uint32_t a[2][4];
            const int c = ks * 8 + lc;
            #pragma unroll
            for (int mt = 0; mt < 2; ++mt) {
                const int r = wrow * 32 + mt * 16 + lr;
                a[mt][0] = __float_as_uint(Qs[r * 68 + c]);
                a[mt][1] = __float_as_uint(Qs[(r + 8) * 68 + c]);
                a[mt][2] = __float_as_uint(Qs[r * 68 + c + 4]);
                a[mt][3] = __float_as_uint(Qs[(r + 8) * 68 + c + 4]);
            }
            #pragma unroll
            for (int nt = 0; nt < 8; ++nt) {
                const int n = wcol * 64 + nt * 8 + lr;
                uint32_t b[2];
                b[0] = __float_as_uint(Ks[n * 68 + c]);
                b[1] = __float_as_uint(Ks[n * 68 + c + 4]);
                mma_tf32(s_acc[0][nt], a[0], b);
                mma_tf32(s_acc[1][nt], a[1], b);
            }
        }
        #pragma unroll
        for (int mt = 0; mt < 2; ++mt) {
            const int r = wrow * 32 + mt * 16 + lr;
            #pragma unroll
            for (int nt = 0; nt < 8; ++nt) {
                const int col = wcol * 64 + nt * 8 + 2 * lc;
                float2 v0; v0.x = s_acc[mt][nt][0]; v0.y = s_acc[mt][nt][1];
                float2 v1; v1.x = s_acc[mt][nt][2]; v1.y = s_acc[mt][nt][3];
                *(float2*)&Ss[r * 132 + col] = v0;
                *(float2*)&Ss[(r + 8) * 132 + col] = v1;
            }
        }
        __syncthreads();

        {
            const int row = tid >> 1, half = tid & 1;
            const int qq = qb * 128 + row;
            const int colbase = half * 64;
            float mx = -1e30f;
            #pragma unroll
            for (int c4 = 0; c4 < 64; c4 += 4) {
                float4 s4 = *(float4*)&Ss[row * 132 + colbase + c4];
                const int kk = kb * 128 + colbase + c4;
                s4.x = (kk     <= qq) ? fmaf(slope, (float)(kk     - qq), s4.x) : -1e30f;
                s4.y = (kk + 1 <= qq) ? fmaf(slope, (float)(kk + 1 - qq), s4.y) : -1e30f;
                s4.z = (kk + 2 <= qq) ? fmaf(slope, (float)(kk + 2 - qq), s4.z) : -1e30f;
                s4.w = (kk + 3 <= qq) ? fmaf(slope, (float)(kk + 3 - qq), s4.w) : -1e30f;
                *(float4*)&Ss[row * 132 + colbase + c4] = s4;
                mx = fmaxf(mx, fmaxf(fmaxf(s4.x, s4.y), fmaxf(s4.z, s4.w)));
            }
            mx = fmaxf(mx, __shfl_xor_sync(0xffffffffu, mx, 1));
            const float m_old = m_sh[row];
            const float m_new = fmaxf(m_old, mx);
            float sum = 0.f;
            #pragma unroll
            for (int c4 = 0; c4 < 64; c4 += 4) {
                float4 s4 = *(float4*)&Ss[row * 132 + colbase + c4];
                s4.x = fexp(s4.x - m_new); s4.y = fexp(s4.y - m_new);
                s4.z = fexp(s4.z - m_new); s4.w = fexp(s4.w - m_new);
                *(float4*)&Ss[row * 132 + colbase + c4] = s4;
                sum += (s4.x + s4.y) + (s4.z + s4.w);
            }
            sum += __shfl_xor_sync(0xffffffffu, sum, 1);
            if (half == 0) {
                const float alpha = fexp(m_old - m_new);
                m_sh[row] = m_new;
                l_sh[row] = l_sh[row] * alpha + sum;
                a_sh[row] = alpha;
            }
        }
        __syncthreads();

        #pragma unroll
        for (int mt = 0; mt < 2; ++mt) {
            const float a0 = a_sh[wrow * 32 + mt * 16 + lr];
            const float a1 = a_sh[wrow * 32 + mt * 16 + lr + 8];
            #pragma unroll
            for (int nt = 0; nt < 4; ++nt) {
                o_acc[mt][nt][0] *= a0; o_acc[mt][nt][1] *= a0;
                o_acc[mt][nt][2] *= a1; o_acc[mt][nt][3] *= a1;
            }
        }
        #pragma unroll
        for (int ks = 0; ks < 16; ++ks) {
            uint32_t a[2][4];
            const int c = ks * 8 + lc;
            #pragma unroll
            for (int mt = 0; mt < 2; ++mt) {
                const int r = wrow * 32 + mt * 16 + lr;
                a[mt][0] = __float_as_uint(Ss[r * 132 + c]);
                a[mt][1] = __float_as_uint(Ss[(r + 8) * 132 + c]);
                a[mt][2] = __float_as_uint(Ss[r * 132 + c + 4]);
                a[mt][3] = __float_as_uint(Ss[(r + 8) * 132 + c + 4]);
            }
            #pragma unroll
            for (int nt = 0; nt < 4; ++nt) {
                const int n = wcol * 32 + nt * 8 + lr;
                uint32_t b[2];
                b[0] = __float_as_uint(VsT[n * 132 + c]);
                b[1] = __float_as_uint(VsT[n * 132 + c + 4]);
                mma_tf32(o_acc[0][nt], a[0], b);
                mma_tf32(o_acc[1][nt], a[1], b);
            }
        }
    }

    // epilogue: O / l -> bf16 hi/lo
    #pragma unroll
    for (int mt = 0; mt < 2; ++mt) {
        const int r = wrow * 32 + mt * 16 + lr;
        const float inv0 = 1.f / l_sh[r];
        const float inv1 = 1.f / l_sh[r + 8];
        #pragma unroll
        for (int nt = 0; nt < 4; ++nt) {
            const int col = h * 64 + wcol * 32 + nt * 8 + 2 * lc;
            float v0x = o_acc[mt][nt][0] * inv0, v0y = o_acc[mt][nt][1] * inv0;
            float v1x = o_acc[mt][nt][2] * inv1, v1y = o_acc[mt][nt][3] * inv1;
            size_t i0 = (size_t)(qb * 128 + r) * D_MODEL + col;
            size_t i1 = (size_t)(qb * 128 + r + 8) * D_MODEL + col;
            *(uint32_t*)&OH[i0] = bfpack(v0x, v0y);
            *(uint32_t*)&OL[i0] = bfpack(v0x - bfhi(v0x), v0y - bfhi(v0y));
            *(uint32_t*)&OH[i1] = bfpack(v1x, v1y);
            *(uint32_t*)&OL[i1] = bfpack(v1x - bfhi(v1x), v1y - bfhi(v1y));
        }
    }
}

// ---------------- QKV output: fp32 (attention consumes fp32) ----------------
// reuse bgemm with OUT_HILO=false

// ---------------- launch ----------------
extern "C" void kernel_launch(void* const* d_in, const int* in_sizes, int n_in,
                              void* d_out, int out_size) {
    const float* x   = (const float*)d_in[0];
    const float* wq  = (const float*)d_in[3];
    const float* bq  = (const float*)d_in[4];
    const float* wk  = (const float*)d_in[5];
    const float* bk  = (const float*)d_in[6];
    const float* wv  = (const float*)d_in[7];
    const float* bv  = (const float*)d_in[8];
    const float* wo  = (const float*)d_in[9];
    const float* bo  = (const float*)d_in[10];
    const float* w1  = (const float*)d_in[11];
    const float* b1  = (const float*)d_in[12];
    const float* w2  = (const float*)d_in[13];
    const float* b2  = (const float*)d_in[14];
    const float* g1  = (const float*)d_in[15];
    const float* be1 = (const float*)d_in[16];
    const float* g2  = (const float*)d_in[17];
    const float* be2 = (const float*)d_in[18];
    float* out = (float*)d_out;

    float *p_q, *p_k, *p_v, *p_x1;
    bf16 *p_xnh, *p_xnl, *p_ah, *p_al, *p_hh, *p_hl;
    bf16 *p_wqh, *p_wql, *p_wkh, *p_wkl, *p_wvh, *p_wvl, *p_woh, *p_wol;
    bf16 *p_w1h, *p_w1l, *p_w2h, *p_w2l;
    cudaGetSymbolAddress((void**)&p_q,   g_q);
    cudaGetSymbolAddress((void**)&p_k,   g_k);
    cudaGetSymbolAddress((void**)&p_v,   g_v);
    cudaGetSymbolAddress((void**)&p_x1,  g_x1);
    cudaGetSymbolAddress((void**)&p_xnh, g_xnh);
    cudaGetSymbolAddress((void**)&p_xnl, g_xnl);
    cudaGetSymbolAddress((void**)&p_ah,  g_ah);
    cudaGetSymbolAddress((void**)&p_al,  g_al);
    cudaGetSymbolAddress((void**)&p_hh,  g_hh);
    cudaGetSymbolAddress((void**)&p_hl,  g_hl);
    cudaGetSymbolAddress((void**)&p_wqh, g_wqh);
    cudaGetSymbolAddress((void**)&p_wql, g_wql);
    cudaGetSymbolAddress((void**)&p_wkh, g_wkh);
    cudaGetSymbolAddress((void**)&p_wkl, g_wkl);
    cudaGetSymbolAddress((void**)&p_wvh, g_wvh);
    cudaGetSymbolAddress((void**)&p_wvl, g_wvl);
    cudaGetSymbolAddress((void**)&p_woh, g_woh);
    cudaGetSymbolAddress((void**)&p_wol, g_wol);
    cudaGetSymbolAddress((void**)&p_w1h, g_w1h);
    cudaGetSymbolAddress((void**)&p_w1l, g_w1l);
    cudaGetSymbolAddress((void**)&p_w2h, g_w2h);
    cudaGetSymbolAddress((void**)&p_w2l, g_w2l);

    cudaFuncSetAttribute(bgemm<0, false, false>, cudaFuncAttributeMaxDynamicSharedMemorySize, SMEM_G);
    cudaFuncSetAttribute(bgemm<0, true,  false>, cudaFuncAttributeMaxDynamicSharedMemorySize, SMEM_G);
    cudaFuncSetAttribute(bgemm<1, false, true >, cudaFuncAttributeMaxDynamicSharedMemorySize, SMEM_G);
    cudaFuncSetAttribute(attn_mma, cudaFuncAttributeMaxDynamicSharedMemorySize, SMEM_ATTN);

    dim3 cb(32, 8);
    // weight converts (fp32 [K][N] -> bf16 hi/lo [N][K])
    wconv<<<dim3(D_MODEL / 32, D_MODEL / 32), cb>>>(wq, p_wqh, p_wql, D_MODEL, D_MODEL);
    wconv<<<dim3(D_MODEL / 32, D_MODEL / 32), cb>>>(wk, p_wkh, p_wkl, D_MODEL, D_MODEL);
    wconv<<<dim3(D_MODEL / 32, D_MODEL / 32), cb>>>(wv, p_wvh, p_wvl, D_MODEL, D_MODEL);
    wconv<<<dim3(D_MODEL / 32, D_MODEL / 32), cb>>>(wo, p_woh, p_wol, D_MODEL, D_MODEL);
    wconv<<<dim3(FFN_DIM / 32, D_MODEL / 32), cb>>>(w1, p_w1h, p_w1l, D_MODEL, FFN_DIM);
    wconv<<<dim3(D_MODEL / 32, FFN_DIM / 32), cb>>>(w2, p_w2h, p_w2l, FFN_DIM, D_MODEL);

    // LN1 -> xn hi/lo
    ln_kernel<<<T_SEQ, 256>>>(x, g1, be1, p_xnh, p_xnl);

    // fused QKV -> fp32 q,k,v
    bgemm<0, false, false><<<dim3(D_MODEL / 128, T_SEQ / 128, 3), 256, SMEM_G>>>(
        p_xnh, p_xnl, p_wqh, p_wql, p_wkh, p_wkl, p_wvh, p_wvl,
        bq, bk, bv, nullptr, p_q, p_k, p_v, nullptr, D_MODEL, D_MODEL);

    // attention -> bf16 hi/lo
    attn_mma<<<dim3(T_SEQ / 128, N_HEADS), 256, SMEM_ATTN>>>(p_q, p_k, p_v, p_ah, p_al);

    // O projection + residual(x) -> x1 fp32
    bgemm<0, true, false><<<dim3(D_MODEL / 128, T_SEQ / 128, 1), 256, SMEM_G>>>(
        p_ah, p_al, p_woh, p_wol, p_woh, p_wol, p_woh, p_wol,
        bo, bo, bo, x, p_x1, p_x1, p_x1, nullptr, D_MODEL, D_MODEL);

    // LN2 -> xn hi/lo
    ln_kernel<<<T_SEQ, 256>>>(p_x1, g2, be2, p_xnh, p_xnl);

    // FFN1 + GELU -> h hi/lo
    bgemm<1, false, true><<<dim3(FFN_DIM / 128, T_SEQ / 128, 1), 256, SMEM_G>>>(
        p_xnh, p_xnl, p_w1h, p_w1l, p_w1h, p_w1l, p_w1h, p_w1l,
        b1, b1, b1, nullptr, p_hh, p_hh, p_hh, p_hl, FFN_DIM, D_MODEL);

    // FFN2 + residual(x1) -> out fp32
    bgemm<0, true, false><<<dim3(D_MODEL / 128, T_SEQ / 128, 1), 256, SMEM_G>>>(
        p_hh, p_hl, p_w2h, p_w2l, p_w2h, p_w2l, p_w2h, p_w2l,
        b2, b2, b2, p_x1, out, out, out, nullptr, D_MODEL, FFN_DIM);
}

// round 6
// speedup vs baseline: 1.6898x; 1.0871x over previous
#include <cuda_runtime.h>
#include <cuda_bf16.h>
#include <math.h>
#include <stdint.h>

#define T_SEQ 2048
#define D_MODEL 1024
#define N_HEADS 16
#define HEAD_DIM 64
#define FFN_DIM 4096
typedef __nv_bfloat16 bf16;

// ---------------- scratch ----------------
__device__ float g_q[T_SEQ * D_MODEL];
__device__ float g_k[T_SEQ * D_MODEL];
__device__ float g_v[T_SEQ * D_MODEL];
__device__ float g_x1[T_SEQ * D_MODEL];
__device__ bf16  g_xnh[T_SEQ * D_MODEL];
__device__ bf16  g_xnl[T_SEQ * D_MODEL];
__device__ bf16  g_ah[T_SEQ * D_MODEL];
__device__ bf16  g_al[T_SEQ * D_MODEL];
__device__ bf16  g_hh[T_SEQ * FFN_DIM];
__device__ bf16  g_hl[T_SEQ * FFN_DIM];
// pre-split weights, ORIGINAL [K][N] layout (no transpose needed w/ ldmatrix.trans)
__device__ bf16 g_wqh[D_MODEL * D_MODEL], g_wql[D_MODEL * D_MODEL];
__device__ bf16 g_wkh[D_MODEL * D_MODEL], g_wkl[D_MODEL * D_MODEL];
__device__ bf16 g_wvh[D_MODEL * D_MODEL], g_wvl[D_MODEL * D_MODEL];
__device__ bf16 g_woh[D_MODEL * D_MODEL], g_wol[D_MODEL * D_MODEL];
__device__ bf16 g_w1h[FFN_DIM * D_MODEL], g_w1l[FFN_DIM * D_MODEL];
__device__ bf16 g_w2h[D_MODEL * FFN_DIM], g_w2l[D_MODEL * FFN_DIM];

// ---------------- helpers ----------------
__device__ __forceinline__ uint32_t smem_u32(const void* p) {
    uint32_t a;
    asm("{ .reg .u64 t; cvta.to.shared.u64 t, %1; cvt.u32.u64 %0, t; }" : "=r"(a) : "l"(p));
    return a;
}
__device__ __forceinline__ void cp16(uint32_t s, const void* g) {
    asm volatile("cp.async.cg.shared.global [%0], [%1], 16;" :: "r"(s), "l"(g));
}
#define CP_COMMIT() asm volatile("cp.async.commit_group;" ::: "memory")
#define CP_WAIT(n)  asm volatile("cp.async.wait_group %0;" :: "n"(n) : "memory")

__device__ __forceinline__ void ldsm4(uint32_t* r, uint32_t addr) {
    asm volatile("ldmatrix.sync.aligned.m8n8.x4.shared.b16 {%0,%1,%2,%3}, [%4];"
        : "=r"(r[0]), "=r"(r[1]), "=r"(r[2]), "=r"(r[3]) : "r"(addr));
}
__device__ __forceinline__ void ldsm4t(uint32_t* r, uint32_t addr) {
    asm volatile("ldmatrix.sync.aligned.m8n8.x4.trans.shared.b16 {%0,%1,%2,%3}, [%4];"
        : "=r"(r[0]), "=r"(r[1]), "=r"(r[2]), "=r"(r[3]) : "r"(addr));
}
__device__ __forceinline__ void mma_bf16(float* d, const uint32_t* a, const uint32_t* b) {
    asm volatile(
        "mma.sync.aligned.m16n8k16.row.col.f32.bf16.bf16.f32 "
        "{%0,%1,%2,%3}, {%4,%5,%6,%7}, {%8,%9}, {%0,%1,%2,%3};"
        : "+f"(d[0]), "+f"(d[1]), "+f"(d[2]), "+f"(d[3])
        : "r"(a[0]), "r"(a[1]), "r"(a[2]), "r"(a[3]), "r"(b[0]), "r"(b[1]));
}
__device__ __forceinline__ void mma_tf32(float* d, const uint32_t* a, const uint32_t* b) {
    asm volatile(
        "mma.sync.aligned.m16n8k8.row.col.f32.tf32.tf32.f32 "
        "{%0,%1,%2,%3}, {%4,%5,%6,%7}, {%8,%9}, {%0,%1,%2,%3};"
        : "+f"(d[0]), "+f"(d[1]), "+f"(d[2]), "+f"(d[3])
        : "r"(a[0]), "r"(a[1]), "r"(a[2]), "r"(a[3]), "r"(b[0]), "r"(b[1]));
}
__device__ __forceinline__ uint32_t bfpack(float a, float b) {
    __nv_bfloat162 t = __floats2bfloat162_rn(a, b);
    return *reinterpret_cast<uint32_t*>(&t);
}
__device__ __forceinline__ float bfhi(float v) {
    return __bfloat162float(__float2bfloat16(v));
}
__device__ __forceinline__ float fexp(float x) {
    float y = fmaxf(x * 1.4426950408889634f, -125.0f);
    float r = rintf(y);
    float f = y - r;
    float p = 1.3333558146e-3f;
    p = fmaf(p, f, 9.6181291076e-3f);
    p = fmaf(p, f, 5.5504108665e-2f);
    p = fmaf(p, f, 2.4022650696e-1f);
    p = fmaf(p, f, 6.9314718056e-1f);
    p = fmaf(p, f, 1.0f);
    return __int_as_float(__float_as_int(p) + (((int)r) << 23));
}

// ---------------- weight split (streaming, no transpose) ----------------
__global__ void wsplit(const float* __restrict__ W, bf16* __restrict__ H,
                       bf16* __restrict__ L) {
    const size_t i = ((size_t)blockIdx.x * 256 + threadIdx.x) * 4;
    float4 v = *(const float4*)&W[i];
    uint2 hh, ll;
    hh.x = bfpack(v.x, v.y); hh.y = bfpack(v.z, v.w);
    ll.x = bfpack(v.x - bfhi(v.x), v.y - bfhi(v.y));
    ll.y = bfpack(v.z - bfhi(v.z), v.w - bfhi(v.w));
    *(uint2*)&H[i] = hh;
    *(uint2*)&L[i] = ll;
}

// ---------------- LayerNorm -> bf16 hi/lo ----------------
__global__ void ln_kernel(const float* __restrict__ x, const float* __restrict__ g,
                          const float* __restrict__ b, bf16* __restrict__ yh,
                          bf16* __restrict__ yl) {
    const int row = blockIdx.x, tid = threadIdx.x;
    const float4 xv = *(const float4*)&x[(size_t)row * D_MODEL + tid * 4];
    float s  = (xv.x + xv.y) + (xv.z + xv.w);
    float s2 = (xv.x * xv.x + xv.y * xv.y) + (xv.z * xv.z + xv.w * xv.w);
    __shared__ float red0[8], red1[8];
    #pragma unroll
    for (int o = 16; o > 0; o >>= 1) {
        s  += __shfl_down_sync(0xffffffffu, s, o);
        s2 += __shfl_down_sync(0xffffffffu, s2, o);
    }
    const int w = tid >> 5, l = tid & 31;
    if (l == 0) { red0[w] = s; red1[w] = s2; }
    __syncthreads();
    if (w == 0) {
        s  = (l < 8) ? red0[l] : 0.f;
        s2 = (l < 8) ? red1[l] : 0.f;
        #pragma unroll
        for (int o = 4; o > 0; o >>= 1) {
            s  += __shfl_down_sync(0xffffffffu, s, o);
            s2 += __shfl_down_sync(0xffffffffu, s2, o);
        }
        if (l == 0) { red0[0] = s; red1[0] = s2; }
    }
    __syncthreads();
    const float mu  = red0[0] * (1.f / D_MODEL);
    const float var = red1[0] * (1.f / D_MODEL) - mu * mu;
    const float inv = rsqrtf(var + 1e-5f);
    const float4 gv = *(const float4*)&g[tid * 4];
    const float4 bv = *(const float4*)&b[tid * 4];
    float o0 = (xv.x - mu) * inv * gv.x + bv.x;
    float o1 = (xv.y - mu) * inv * gv.y + bv.y;
    float o2 = (xv.z - mu) * inv * gv.z + bv.z;
    float o3 = (xv.w - mu) * inv * gv.w + bv.w;
    uint2 H, L;
    H.x = bfpack(o0, o1); H.y = bfpack(o2, o3);
    L.x = bfpack(o0 - bfhi(o0), o1 - bfhi(o1));
    L.y = bfpack(o2 - bfhi(o2), o3 - bfhi(o3));
    *(uint2*)&yh[(size_t)row * D_MODEL + tid * 4] = H;
    *(uint2*)&yl[(size_t)row * D_MODEL + tid * 4] = L;
}

// ---------------- bf16x3 mma GEMM with ldmatrix ----------------
// C = act(A @ W + bias) (+Res). A: [M][K] bf16 hi/lo; W: [K][N] bf16 hi/lo.
// Tile 128 x BN x 32; 8 warps (4 row x 2 col); m16n8k16; cp.async double buffer.
// A smem: [m][k] rows 64B data padded to 80B (banks 20r mod 32: conflict-free).
// B smem: [k][n] rows BN*2 data padded +16B (banks 4r pattern: conflict-free, trans ldsm).
#define ARR_A 10240

template<int ACT, bool HAS_RES, bool OUT_HILO, int BN>
__global__ void __launch_bounds__(256, 2)
bgemm(const bf16* __restrict__ Ah, const bf16* __restrict__ Al,
      const bf16* __restrict__ W0h, const bf16* __restrict__ W0l,
      const bf16* __restrict__ W1h, const bf16* __restrict__ W1l,
      const bf16* __restrict__ W2h, const bf16* __restrict__ W2l,
      const float* __restrict__ b0, const float* __restrict__ b1, const float* __restrict__ b2,
      const float* __restrict__ Res,
      void* __restrict__ C0, void* __restrict__ C1, void* __restrict__ C2,
      void* __restrict__ Clo,
      int N, int K) {
    constexpr int B_STR = BN * 2 + 16;          // bytes per B smem row
    constexpr int ARR_B = 32 * B_STR;
    constexpr int STAGE = 2 * ARR_A + 2 * ARR_B;
    constexpr int NT = BN / 16;                  // n-tiles (8 cols) per warp
    constexpr int NPAIR = NT / 2;

    extern __shared__ char smem[];
    const int z = blockIdx.z;
    const bf16* Wh    = (z == 0) ? W0h : (z == 1) ? W1h : W2h;
    const bf16* Wl    = (z == 0) ? W0l : (z == 1) ? W1l : W2l;
    const float* bias = (z == 0) ? b0 : (z == 1) ? b1 : b2;
    void* Cv          = (z == 0) ? C0 : (z == 1) ? C1 : C2;

    const int m0 = blockIdx.y * 128;
    const int n0 = blockIdx.x * BN;
    const int tid = threadIdx.x;
    const int wid = tid >> 5, lane = tid & 31;
    const int wrow = wid & 3, wcol = wid >> 2;
    const int lr = lane >> 2, lc = lane & 3;
    const int lrow = lane & 7, sub = lane >> 3;

    const uint32_t sbase = smem_u32(smem);
    const int NKB = K >> 5;

    // per-lane ldmatrix base offsets
    const uint32_t aoff = (uint32_t)(wrow * 32 + lrow + 8 * (sub & 1)) * 80u + 16u * (sub >> 1);
    const uint32_t boff = (uint32_t)(lrow + 8 * (sub & 1)) * (uint32_t)B_STR +
                          (uint32_t)(wcol * (BN / 2) + 8 * (sub >> 1)) * 2u;

    auto load_stage = [&](int kb, int s) {
        const int k0 = kb << 5;
        const uint32_t st = sbase + s * STAGE;
        #pragma unroll
        for (int f = tid; f < 512; f += 256) {
            const int r = f >> 2, cc = f & 3;
            const uint32_t doff = (uint32_t)r * 80u + (uint32_t)cc * 16u;
            const size_t go = (size_t)(m0 + r) * K + k0 + cc * 8;
            cp16(st + doff, Ah + go);
            cp16(st + ARR_A + doff, Al + go);
        }
        #pragma unroll
        for (int f = tid; f < 32 * (BN / 8); f += 256) {
            const int r = f / (BN / 8), cc = f % (BN / 8);
            const uint32_t doff = (uint32_t)r * (uint32_t)B_STR + (uint32_t)cc * 16u;
            const size_t go = (size_t)(k0 + r) * N + n0 + cc * 8;
            cp16(st + 2 * ARR_A + doff, Wh + go);
            cp16(st + 2 * ARR_A + ARR_B + doff, Wl + go);
        }
    };

    float acc[2][NT][4];
    #pragma unroll
    for (int mt = 0; mt < 2; ++mt)
        #pragma unroll
        for (int nt = 0; nt < NT; ++nt)
            #pragma unroll
            for (int i = 0; i < 4; ++i) acc[mt][nt][i] = 0.f;

    load_stage(0, 0);
    CP_COMMIT();

    for (int kb = 0; kb < NKB; ++kb) {
        const int s = kb & 1;
        if (kb + 1 < NKB) {
            load_stage(kb + 1, s ^ 1);
            CP_COMMIT();
            CP_WAIT(1);
        } else {
            CP_WAIT(0);
        }
        __syncthreads();

        const uint32_t stg = sbase + s * STAGE;
        #pragma unroll
        for (int kstep = 0; kstep < 2; ++kstep) {
            uint32_t ah[2][4], al[2][4];
            #pragma unroll
            for (int mt = 0; mt < 2; ++mt) {
                ldsm4(ah[mt], stg + aoff + mt * 1280 + kstep * 32);
                ldsm4(al[mt], stg + ARR_A + aoff + mt * 1280 + kstep * 32);
            }
            uint32_t bh[NT][2], bl[NT][2];
            #pragma unroll
            for (int p = 0; p < NPAIR; ++p) {
                uint32_t t[4];
                ldsm4t(t, stg + 2 * ARR_A + boff + p * 32 + kstep * 16 * B_STR);
                bh[2 * p][0] = t[0]; bh[2 * p][1] = t[1];
                bh[2 * p + 1][0] = t[2]; bh[2 * p + 1][1] = t[3];
                ldsm4t(t, stg + 2 * ARR_A + ARR_B + boff + p * 32 + kstep * 16 * B_STR);
                bl[2 * p][0] = t[0]; bl[2 * p][1] = t[1];
                bl[2 * p + 1][0] = t[2]; bl[2 * p + 1][1] = t[3];
            }
            #pragma unroll
            for (int nt = 0; nt < NT; ++nt) {
                mma_bf16(acc[0][nt], ah[0], bh[nt]);
                mma_bf16(acc[1][nt], ah[1], bh[nt]);
                mma_bf16(acc[0][nt], al[0], bh[nt]);
                mma_bf16(acc[1][nt], al[1], bh[nt]);
                mma_bf16(acc[0][nt], ah[0], bl[nt]);
                mma_bf16(acc[1][nt], ah[1], bl[nt]);
            }
        }
        __syncthreads();
    }

    // epilogue
    #pragma unroll
    for (int nt = 0; nt < NT; ++nt) {
        const int col = n0 + wcol * (BN / 2) + nt * 8 + lc * 2;
        const float2 bv = *(const float2*)&bias[col];
        #pragma unroll
        for (int mt = 0; mt < 2; ++mt) {
            const int row = m0 + wrow * 32 + mt * 16 + lr;
            #pragma unroll
            for (int half = 0; half < 2; ++half) {
                const int r = row + half * 8;
                float vx = acc[mt][nt][half * 2 + 0] + bv.x;
                float vy = acc[mt][nt][half * 2 + 1] + bv.y;
                if (ACT == 1) {
                    vx = 0.5f * vx * (1.0f + erff(vx * 0.7071067811865475f));
                    vy = 0.5f * vy * (1.0f + erff(vy * 0.7071067811865475f));
                }
                if (HAS_RES) {
                    float2 rv = *(const float2*)&Res[(size_t)r * N + col];
                    vx += rv.x; vy += rv.y;
                }
                if (OUT_HILO) {
                    bf16* Ch = (bf16*)Cv;
                    bf16* Cl = (bf16*)Clo;
                    *(uint32_t*)&Ch[(size_t)r * N + col] = bfpack(vx, vy);
                    *(uint32_t*)&Cl[(size_t)r * N + col] =
                        bfpack(vx - bfhi(vx), vy - bfhi(vy));
                } else {
                    float2 o; o.x = vx; o.y = vy;
                    *(float2*)&((float*)Cv)[(size_t)r * N + col] = o;
                }
            }
        }
    }
}

// ---------------- flash attention on mma.sync tf32 (out: bf16 hi/lo) ----------------
#define AT_QS   0
#define AT_KS   (128 * 68)
#define AT_VST  (AT_KS + 128 * 68)
#define AT_SS   (AT_VST + 64 * 132)
#define AT_MST  (AT_SS + 128 * 132)
#define AT_FLOATS (AT_MST + 3 * 128)
#define SMEM_ATTN (AT_FLOATS * 4)

__global__ void __launch_bounds__(256, 1)
attn_mma(const float* __restrict__ Q, const float* __restrict__ K,
         const float* __restrict__ V, bf16* __restrict__ OH, bf16* __restrict__ OL) {
    extern __shared__ float sm[];
    float* Qs   = sm + AT_QS;
    float* Ks   = sm + AT_KS;
    float* VsT  = sm + AT_VST;
    float* Ss   = sm + AT_SS;
    float* m_sh = sm + AT_MST;
    float* l_sh = m_sh + 128;
    float* a_sh = l_sh + 128;

    const int qb = gridDim.x - 1 - blockIdx.x;
    const int h  = blockIdx.y;
    const int tid = threadIdx.x;
    const int wid = tid >> 5, lane = tid & 31;
    const int lr = lane >> 2, lc = lane & 3;
    const int wrow = wid & 3, wcol = wid >> 2;

    #pragma unroll
    for (int i = 0; i < 8; ++i) {
        int f = tid + i * 256;
        int r = f >> 4, c4 = (f & 15) << 2;
        float4 v = *(const float4*)&Q[(size_t)(qb * 128 + r) * D_MODEL + h * 64 + c4];
        float* dst = &Qs[r * 68 + c4];
        dst[0] = v.x * 0.125f; dst[1] = v.y * 0.125f;
        dst[2] = v.z * 0.125f; dst[3] = v.w * 0.125f;
    }
    if (tid < 128) { m_sh[tid] = -1e30f; l_sh[tid] = 0.f; }

    float o_acc[2][4][4] = {};
    const float slope = exp2f(-0.5f * (float)(h + 1));

    for (int kb = 0; kb <= qb; ++kb) {
        __syncthreads();
        #pragma unroll
        for (int i = 0; i < 8; ++i) {
            int f = tid + i * 256;
            int r = f >> 4, c4 = (f & 15) << 2;
            float4 v = *(const float4*)&K[(size_t)(kb * 128 + r) * D_MODEL + h * 64 + c4];
            float* dst = &Ks[r * 68 + c4];
            dst[0] = v.x; dst[1] = v.y; dst[2] = v.z; dst[3] = v.w;
        }
        {
            const int d = tid & 63, k0 = tid >> 6;
            const float* vp = V + (size_t)(kb * 128 + k0) * D_MODEL + h * 64 + d;
            #pragma unroll
            for (int i = 0; i < 32; ++i)
                VsT[d * 132 + k0 + i * 4] = vp[(size_t)i * 4 * D_MODEL];
        }
        __syncthreads();

        float s_acc[2][8][4] = {};
        #pragma unroll
        for (int ks = 0; ks < 8; ++ks) {
            uint32_t a[2][4];
            const int c = ks * 8 + lc;
            #pragma unroll
            for (int mt = 0; mt < 2; ++mt) {
                const int r = wrow * 32 + mt * 16 + lr;
                a[mt][0] = __float_as_uint(Qs[r * 68 + c]);
                a[mt][1] = __float_as_uint(Qs[(r + 8) * 68 + c]);
                a[mt][2] = __float_as_uint(Qs[r * 68 + c + 4]);
                a[mt][3] = __float_as_uint(Qs[(r + 8) * 68 + c + 4]);
            }
            #pragma unroll
            for (int nt = 0; nt < 8; ++nt) {
                const int n = wcol * 64 + nt * 8 + lr;
                uint32_t b[2];
                b[0] = __float_as_uint(Ks[n * 68 + c]);
                b[1] = __float_as_uint(Ks[n * 68 + c + 4]);
                mma_tf32(s_acc[0][nt], a[0], b);
                mma_tf32(s_acc[1][nt], a[1], b);
            }
        }
        #pragma unroll
        for (int mt = 0; mt < 2; ++mt) {
            const int r = wrow * 32 + mt * 16 + lr;
            #pragma unroll
            for (int nt = 0; nt < 8; ++nt) {
                const int col = wcol * 64 + nt * 8 + 2 * lc;
                float2 v0; v0.x = s_acc[mt][nt][0]; v0.y = s_acc[mt][nt][1];
                float2 v1; v1.x = s_acc[mt][nt][2]; v1.y = s_acc[mt][nt][3];
                *(float2*)&Ss[r * 132 + col] = v0;
                *(float2*)&Ss[(r + 8) * 132 + col] = v1;
            }
        }
        __syncthreads();

        {
            const int row = tid >> 1, half = tid & 1;
            const int qq = qb * 128 + row;
            const int colbase = half * 64;
            float mx = -1e30f;
            #pragma unroll
            for (int c4 = 0; c4 < 64; c4 += 4) {
                float4 s4 = *(float4*)&Ss[row * 132 + colbase + c4];
                const int kk = kb * 128 + colbase + c4;
                s4.x = (kk     <= qq) ? fmaf(slope, (float)(kk     - qq), s4.x) : -1e30f;
                s4.y = (kk + 1 <= qq) ? fmaf(slope, (float)(kk + 1 - qq), s4.y) : -1e30f;
                s4.z = (kk + 2 <= qq) ? fmaf(slope, (float)(kk + 2 - qq), s4.z) : -1e30f;
                s4.w = (kk + 3 <= qq) ? fmaf(slope, (float)(kk + 3 - qq), s4.w) : -1e30f;
                *(float4*)&Ss[row * 132 + colbase + c4] = s4;
                mx = fmaxf(mx, fmaxf(fmaxf(s4.x, s4.y), fmaxf(s4.z, s4.w)));
            }
            mx = fmaxf(mx, __shfl_xor_sync(0xffffffffu, mx, 1));
            const float m_old = m_sh[row];
            const float m_new = fmaxf(m_old, mx);
            float sum = 0.f;
            #pragma unroll
            for (int c4 = 0; c4 < 64; c4 += 4) {
                float4 s4 = *(float4*)&Ss[row * 132 + colbase + c4];
                s4.x = fexp(s4.x - m_new); s4.y = fexp(s4.y - m_new);
                s4.z = fexp(s4.z - m_new); s4.w = fexp(s4.w - m_new);
                *(float4*)&Ss[row * 132 + colbase + c4] = s4;
                sum += (s4.x + s4.y) + (s4.z + s4.w);
            }
            sum += __shfl_xor_sync(0xffffffffu, sum, 1);
            if (half == 0) {
                const float alpha = fexp(m_old - m_new);
                m_sh[row] = m_new;
                l_sh[row] = l_sh[row] * alpha + sum;
                a_sh[row] = alpha;
            }
        }
        __syncthreads();

        #pragma unroll
        for (int mt = 0; mt < 2; ++mt) {
            const float a0 = a_sh[wrow * 32 + mt * 16 + lr];
            const float a1 = a_sh[wrow * 32 + mt * 16 + lr + 8];
            #pragma unroll
            for (int nt = 0; nt < 4; ++nt) {
                o_acc[mt][nt][0] *= a0; o_acc[mt][nt][1] *= a0;
                o_acc[mt][nt][2] *= a1; o_acc[mt][nt][3] *= a1;
            }
        }
        #pragma unroll
        for (int ks = 0; ks < 16; ++ks) {
            uint32_t a[2][4];
            const int c = ks * 8 + lc;
            #pragma unroll
            for (int mt = 0; mt < 2; ++mt) {
                const int r = wrow * 32 + mt * 16 + lr;
                a[mt][0] = __float_as_uint(Ss[r * 132 + c]);
                a[mt][1] = __float_as_uint(Ss[(r + 8) * 132 + c]);
                a[mt][2] = __float_as_uint(Ss[r * 132 + c + 4]);
                a[mt][3] = __float_as_uint(Ss[(r + 8) * 132 + c + 4]);
            }
            #pragma unroll
            for (int nt = 0; nt < 4; ++nt) {
                const int n = wcol * 32 + nt * 8 + lr;
                uint32_t b[2];
                b[0] = __float_as_uint(VsT[n * 132 + c]);
                b[1] = __float_as_uint(VsT[n * 132 + c + 4]);
                mma_tf32(o_acc[0][nt], a[0], b);
                mma_tf32(o_acc[1][nt], a[1], b);
            }
        }
    }

    #pragma unroll
    for (int mt = 0; mt < 2; ++mt) {
        const int r = wrow * 32 + mt * 16 + lr;
        const float inv0 = 1.f / l_sh[r];
        const float inv1 = 1.f / l_sh[r + 8];
        #pragma unroll
        for (int nt = 0; nt < 4; ++nt) {
            const int col = h * 64 + wcol * 32 + nt * 8 + 2 * lc;
            float v0x = o_acc[mt][nt][0] * inv0, v0y = o_acc[mt][nt][1] * inv0;
            float v1x = o_acc[mt][nt][2] * inv1, v1y = o_acc[mt][nt][3] * inv1;
            size_t i0 = (size_t)(qb * 128 + r) * D_MODEL + col;
            size_t i1 = (size_t)(qb * 128 + r + 8) * D_MODEL + col;
            *(uint32_t*)&OH[i0] = bfpack(v0x, v0y);
            *(uint32_t*)&OL[i0] = bfpack(v0x - bfhi(v0x), v0y - bfhi(v0y));
            *(uint32_t*)&OH[i1] = bfpack(v1x, v1y);
            *(uint32_t*)&OL[i1] = bfpack(v1x - bfhi(v1x), v1y - bfhi(v1y));
        }
    }
}

// ---------------- launch ----------------
extern "C" void kernel_launch(void* const* d_in, const int* in_sizes, int n_in,
                              void* d_out, int out_size) {
    const float* x   = (const float*)d_in[0];
    const float* wq  = (const float*)d_in[3];
    const float* bq  = (const float*)d_in[4];
    const float* wk  = (const float*)d_in[5];
    const float* bk  = (const float*)d_in[6];
    const float* wv  = (const float*)d_in[7];
    const float* bv  = (const float*)d_in[8];
    const float* wo  = (const float*)d_in[9];
    const float* bo  = (const float*)d_in[10];
    const float* w1  = (const float*)d_in[11];
    const float* b1  = (const float*)d_in[12];
    const float* w2  = (const float*)d_in[13];
    const float* b2  = (const float*)d_in[14];
    const float* g1  = (const float*)d_in[15];
    const float* be1 = (const float*)d_in[16];
    const float* g2  = (const float*)d_in[17];
    const float* be2 = (const float*)d_in[18];
    float* out = (float*)d_out;

    float *p_q, *p_k, *p_v, *p_x1;
    bf16 *p_xnh, *p_xnl, *p_ah, *p_al, *p_hh, *p_hl;
    bf16 *p_wqh, *p_wql, *p_wkh, *p_wkl, *p_wvh, *p_wvl, *p_woh, *p_wol;
    bf16 *p_w1h, *p_w1l, *p_w2h, *p_w2l;
    cudaGetSymbolAddress((void**)&p_q,   g_q);
    cudaGetSymbolAddress((void**)&p_k,   g_k);
    cudaGetSymbolAddress((void**)&p_v,   g_v);
    cudaGetSymbolAddress((void**)&p_x1,  g_x1);
    cudaGetSymbolAddress((void**)&p_xnh, g_xnh);
    cudaGetSymbolAddress((void**)&p_xnl, g_xnl);
    cudaGetSymbolAddress((void**)&p_ah,  g_ah);
    cudaGetSymbolAddress((void**)&p_al,  g_al);
    cudaGetSymbolAddress((void**)&p_hh,  g_hh);
    cudaGetSymbolAddress((void**)&p_hl,  g_hl);
    cudaGetSymbolAddress((void**)&p_wqh, g_wqh);
    cudaGetSymbolAddress((void**)&p_wql, g_wql);
    cudaGetSymbolAddress((void**)&p_wkh, g_wkh);
    cudaGetSymbolAddress((void**)&p_wkl, g_wkl);
    cudaGetSymbolAddress((void**)&p_wvh, g_wvh);
    cudaGetSymbolAddress((void**)&p_wvl, g_wvl);
    cudaGetSymbolAddress((void**)&p_woh, g_woh);
    cudaGetSymbolAddress((void**)&p_wol, g_wol);
    cudaGetSymbolAddress((void**)&p_w1h, g_w1h);
    cudaGetSymbolAddress((void**)&p_w1l, g_w1l);
    cudaGetSymbolAddress((void**)&p_w2h, g_w2h);
    cudaGetSymbolAddress((void**)&p_w2l, g_w2l);

    // smem sizes
    const int smem64  = 2 * (2 * ARR_A + 2 * 32 * (64 * 2 + 16));    // 59392
    const int smem128 = 2 * (2 * ARR_A + 2 * 32 * (128 * 2 + 16));   // 75776

    cudaFuncSetAttribute(bgemm<0, false, false, 64>,  cudaFuncAttributeMaxDynamicSharedMemorySize, smem64);
    cudaFuncSetAttribute(bgemm<0, true,  false, 64>,  cudaFuncAttributeMaxDynamicSharedMemorySize, smem64);
    cudaFuncSetAttribute(bgemm<1, false, true,  128>, cudaFuncAttributeMaxDynamicSharedMemorySize, smem128);
    cudaFuncSetAttribute(attn_mma, cudaFuncAttributeMaxDynamicSharedMemorySize, SMEM_ATTN);

    // weight splits (streaming)
    wsplit<<<D_MODEL * D_MODEL / 1024, 256>>>(wq, p_wqh, p_wql);
    wsplit<<<D_MODEL * D_MODEL / 1024, 256>>>(wk, p_wkh, p_wkl);
    wsplit<<<D_MODEL * D_MODEL / 1024, 256>>>(wv, p_wvh, p_wvl);
    wsplit<<<D_MODEL * D_MODEL / 1024, 256>>>(wo, p_woh, p_wol);
    wsplit<<<D_MODEL * FFN_DIM / 1024, 256>>>(w1, p_w1h, p_w1l);
    wsplit<<<D_MODEL * FFN_DIM / 1024, 256>>>(w2, p_w2h, p_w2l);

    // LN1
    ln_kernel<<<T_SEQ, 256>>>(x, g1, be1, p_xnh, p_xnl);

    // fused QKV (BN=64)
    bgemm<0, false, false, 64><<<dim3(D_MODEL / 64, T_SEQ / 128, 3), 256, smem64>>>(
        p_xnh, p_xnl, p_wqh, p_wql, p_wkh, p_wkl, p_wvh, p_wvl,
        bq, bk, bv, nullptr, p_q, p_k, p_v, nullptr, D_MODEL, D_MODEL);

    // attention
    attn_mma<<<dim3(T_SEQ / 128, N_HEADS), 256, SMEM_ATTN>>>(p_q, p_k, p_v, p_ah, p_al);

    // O projection + residual(x) (BN=64)
    bgemm<0, true, false, 64><<<dim3(D_MODEL / 64, T_SEQ / 128, 1), 256, smem64>>>(
        p_ah, p_al, p_woh, p_wol, p_woh, p_wol, p_woh, p_wol,
        bo, bo, bo, x, p_x1, p_x1, p_x1, nullptr, D_MODEL, D_MODEL);

    // LN2
    ln_kernel<<<T_SEQ, 256>>>(p_x1, g2, be2, p_xnh, p_xnl);

    // FFN1 + GELU (BN=128)
    bgemm<1, false, true, 128><<<dim3(FFN_DIM / 128, T_SEQ / 128, 1), 256, smem128>>>(
        p_xnh, p_xnl, p_w1h, p_w1l, p_w1h, p_w1l, p_w1h, p_w1l,
        b1, b1, b1, nullptr, p_hh, p_hh, p_hh, p_hl, FFN_DIM, D_MODEL);

    // FFN2 + residual(x1) (BN=64)
    bgemm<0, true, false, 64><<<dim3(D_MODEL / 64, T_SEQ / 128, 1), 256, smem64>>>(
        p_hh, p_hl, p_w2h, p_w2l, p_w2h, p_w2l, p_w2h, p_w2l,
        b2, b2, b2, p_x1, out, out, out, nullptr, D_MODEL, FFN_DIM);
}